// round 14
// baseline (speedup 1.0000x reference)
#include <cuda_runtime.h>
#include <cstdint>

#define T_STEPS 256
#define BATCH   64
#define INDIM   1024
#define HID     1024
#define G4      4096
#define NCTA2   128   // recurrent CTAs (all co-resident)
#define UPC     8     // hidden units per recurrent CTA
#define KC      128   // k-chunk for h staging
#define MAXROWS 24    // max producer tile-rows (PS=48 -> 24 rows)
#define NT      512   // fused kernel threads

// ---------------- scratch (static device globals; no allocs allowed) --------
__device__ float    g_xg[(size_t)T_STEPS * BATCH * G4];  // 256 MiB input projection
__device__ float    g_h[2][HID][BATCH];                  // TRANSPOSED [k][b], double buffered
__device__ unsigned g_bar_cnt;
__device__ unsigned g_bar_gen;
__device__ unsigned g_c1[8];            // two-level step barrier: group counters
__device__ unsigned g_c2;               // root counter
__device__ unsigned g_gen2;             // generation (== completed steps)
__device__ unsigned g_row_done[MAXROWS];// producer tile-row completion counters

// ---------------- init barrier (self-resetting, proven; used once) ----------
__device__ __forceinline__ void grid_barrier_atomic(unsigned nctas) {
    __syncthreads();
    __threadfence();
    if (threadIdx.x == 0) {
        unsigned gen = *(volatile unsigned*)&g_bar_gen;
        unsigned t = atomicAdd(&g_bar_cnt, 1u);
        if (t == nctas - 1u) {
            *(volatile unsigned*)&g_bar_cnt = 0u;
            __threadfence();
            atomicAdd(&g_bar_gen, 1u);
        } else {
            while (*(volatile unsigned*)&g_bar_gen == gen) { __nanosleep(64); }
        }
        __threadfence();
    }
    __syncthreads();
}

// ---------------- two-level per-step barrier (128 recurrent CTAs) -----------
__device__ __forceinline__ void step_barrier(int cta, int s) {
    __syncthreads();
    __threadfence();
    if (threadIdx.x == 0) {
        unsigned t = atomicAdd(&g_c1[cta >> 4], 1u);
        if (t == 16u * (unsigned)(s + 1) - 1u) {          // last of group
            unsigned t2 = atomicAdd(&g_c2, 1u);
            if (t2 == 8u * (unsigned)(s + 1) - 1u)        // last group
                atomicAdd(&g_gen2, 1u);
        }
        unsigned v;
        do {
            asm volatile("ld.global.cg.u32 %0, [%1];" : "=r"(v) : "l"(&g_gen2));
            if (v < (unsigned)(s + 1)) __nanosleep(32);
        } while (v < (unsigned)(s + 1));
    }
    __threadfence();
    __syncthreads();
}

// ---------------- cp.async helpers ------------------------------------------
__device__ __forceinline__ void cp_async_cg16(void* dst_smem, const void* src) {
    unsigned d = (unsigned)__cvta_generic_to_shared(dst_smem);
    asm volatile("cp.async.cg.shared.global [%0], [%1], 16;\n" :: "r"(d), "l"(src));
}
__device__ __forceinline__ void cp_async_commit() {
    asm volatile("cp.async.commit_group;\n");
}
template <int N>
__device__ __forceinline__ void cp_async_wait() {
    asm volatile("cp.async.wait_group %0;\n" :: "n"(N));
}

#define BM 128
#define BN 128
#define BK 16

// ---------------- GEMM tile body, 256 threads (standalone phase 1) ----------
// EXACT ORDER CONTRACT: per output element, single fp32 accumulator,
// sequential fused-FMA over k = 0..1023 ascending, then +b_ih, then +b_hh.
__device__ __forceinline__ void gemm_tile_body(
    const float* __restrict__ x, const float* __restrict__ Wih,
    const float* __restrict__ bih, const float* __restrict__ bhh,
    int m0, int n0, float* As, float* Bs)
{
    const int tid = threadIdx.x;
    const int tm  = tid >> 4;
    const int tn  = tid & 15;
    const int lk  = tid & 15;
    const int lr  = tid >> 4;

    float acc[8][8];
#pragma unroll
    for (int i = 0; i < 8; i++)
#pragma unroll
        for (int j = 0; j < 8; j++) acc[i][j] = 0.0f;

    float ra[8], rb[8];
#pragma unroll
    for (int p = 0; p < 8; p++) {
        ra[p] = x  [(size_t)(m0 + lr + p * 16) * INDIM + lk];
        rb[p] = Wih[(size_t)(n0 + lr + p * 16) * INDIM + lk];
    }

    for (int it = 0; it < INDIM / BK; it++) {
        const int buf = it & 1;
        float* Ab = As + (buf * BK) * 132;
        float* Bb = Bs + (buf * BK) * 132;
#pragma unroll
        for (int p = 0; p < 8; p++) {
            Ab[lk * 132 + lr + p * 16] = ra[p];
            Bb[lk * 132 + lr + p * 16] = rb[p];
        }
        __syncthreads();

        if (it + 1 < INDIM / BK) {
            const int k0 = (it + 1) * BK;
#pragma unroll
            for (int p = 0; p < 8; p++) {
                ra[p] = x  [(size_t)(m0 + lr + p * 16) * INDIM + k0 + lk];
                rb[p] = Wih[(size_t)(n0 + lr + p * 16) * INDIM + k0 + lk];
            }
        }

#pragma unroll
        for (int k = 0; k < BK; k++) {
            float4 a0 = *(const float4*)&Ab[k * 132 + tm * 8];
            float4 a1 = *(const float4*)&Ab[k * 132 + tm * 8 + 4];
            float4 b0 = *(const float4*)&Bb[k * 132 + tn * 8];
            float4 b1 = *(const float4*)&Bb[k * 132 + tn * 8 + 4];
            float av[8] = {a0.x, a0.y, a0.z, a0.w, a1.x, a1.y, a1.z, a1.w};
            float bv[8] = {b0.x, b0.y, b0.z, b0.w, b1.x, b1.y, b1.z, b1.w};
#pragma unroll
            for (int i = 0; i < 8; i++)
#pragma unroll
                for (int j = 0; j < 8; j++)
                    acc[i][j] = __fmaf_rn(av[i], bv[j], acc[i][j]);
        }
        __syncthreads();
    }

    float bi[8], bh[8];
#pragma unroll
    for (int j = 0; j < 8; j++) {
        int n = n0 + tn * 8 + j;
        bi[j] = bih[n];
        bh[j] = bhh[n];
    }
#pragma unroll
    for (int i = 0; i < 8; i++) {
        float v[8];
#pragma unroll
        for (int j = 0; j < 8; j++)
            v[j] = __fadd_rn(__fadd_rn(acc[i][j], bi[j]), bh[j]);
        size_t row = (size_t)(m0 + tm * 8 + i) * G4 + (n0 + tn * 8);
        *(float4*)&g_xg[row]     = make_float4(v[0], v[1], v[2], v[3]);
        *(float4*)&g_xg[row + 4] = make_float4(v[4], v[5], v[6], v[7]);
    }
}

__global__ void __launch_bounds__(256, 2) gemm_xproj(
    const float* __restrict__ x, const float* __restrict__ Wih,
    const float* __restrict__ bih, const float* __restrict__ bhh)
{
    __shared__ float As[2 * BK * 132];
    __shared__ float Bs[2 * BK * 132];
    gemm_tile_body(x, Wih, bih, bhh,
                   blockIdx.y * BM, blockIdx.x * BN, As, Bs);
}

// ---------------- GEMM tile body, 512 threads (producer role) ---------------
// Same EXACT ORDER CONTRACT; 8x4 microtile per thread.
__device__ __forceinline__ void gemm_tile_body_512(
    const float* __restrict__ x, const float* __restrict__ Wih,
    const float* __restrict__ bih, const float* __restrict__ bhh,
    int m0, int n0, float* As, float* Bs)
{
    const int tid = threadIdx.x;
    const int tm  = tid >> 5;       // 0..15 (8 rows each)
    const int tn  = tid & 31;       // 0..31 (4 cols each)
    const int lk  = tid & 15;       // staging k lane
    const int lr  = tid >> 4;       // staging row lane (0..31)

    float acc[8][4];
#pragma unroll
    for (int i = 0; i < 8; i++)
#pragma unroll
        for (int j = 0; j < 4; j++) acc[i][j] = 0.0f;

    float ra[4], rb[4];
#pragma unroll
    for (int p = 0; p < 4; p++) {
        ra[p] = x  [(size_t)(m0 + lr + p * 32) * INDIM + lk];
        rb[p] = Wih[(size_t)(n0 + lr + p * 32) * INDIM + lk];
    }

    for (int it = 0; it < INDIM / BK; it++) {
        const int buf = it & 1;
        float* Ab = As + (buf * BK) * 132;
        float* Bb = Bs + (buf * BK) * 132;
#pragma unroll
        for (int p = 0; p < 4; p++) {
            Ab[lk * 132 + lr + p * 32] = ra[p];
            Bb[lk * 132 + lr + p * 32] = rb[p];
        }
        __syncthreads();

        if (it + 1 < INDIM / BK) {
            const int k0 = (it + 1) * BK;
#pragma unroll
            for (int p = 0; p < 4; p++) {
                ra[p] = x  [(size_t)(m0 + lr + p * 32) * INDIM + k0 + lk];
                rb[p] = Wih[(size_t)(n0 + lr + p * 32) * INDIM + k0 + lk];
            }
        }

#pragma unroll
        for (int k = 0; k < BK; k++) {
            float4 a0 = *(const float4*)&Ab[k * 132 + tm * 8];      // broadcast
            float4 a1 = *(const float4*)&Ab[k * 132 + tm * 8 + 4];  // broadcast
            float4 b0 = *(const float4*)&Bb[k * 132 + tn * 4];
            float av[8] = {a0.x, a0.y, a0.z, a0.w, a1.x, a1.y, a1.z, a1.w};
            float bv[4] = {b0.x, b0.y, b0.z, b0.w};
#pragma unroll
            for (int i = 0; i < 8; i++)
#pragma unroll
                for (int j = 0; j < 4; j++)
                    acc[i][j] = __fmaf_rn(av[i], bv[j], acc[i][j]);
        }
        __syncthreads();
    }

    float bi[4], bh[4];
#pragma unroll
    for (int j = 0; j < 4; j++) {
        int n = n0 + tn * 4 + j;
        bi[j] = bih[n];
        bh[j] = bhh[n];
    }
#pragma unroll
    for (int i = 0; i < 8; i++) {
        float v[4];
#pragma unroll
        for (int j = 0; j < 4; j++)
            v[j] = __fadd_rn(__fadd_rn(acc[i][j], bi[j]), bh[j]);
        size_t row = (size_t)(m0 + tm * 8 + i) * G4 + (n0 + tn * 4);
        __stcg((float4*)&g_xg[row], make_float4(v[0], v[1], v[2], v[3]));
    }
}

// ---------------- Fused persistent kernel (512 threads) ---------------------
// CTAs [0,128): recurrence, 16 warps (4/SMSP) for latency hiding.
// CTAs [128,128+P): producers for steps [S0,256).
#define SM_W    (HID * 33)            // 33792 floats
#define SM_HS   (KC * BATCH)          // 8192 floats per buffer (16 warps x KC x 4)
#define SM_SPK  (BATCH * 33)
#define SMEM_BYTES ((SM_W + 2 * SM_HS + SM_SPK) * 4)   // 209152 B

extern __shared__ float sm[];

__global__ void __launch_bounds__(NT, 1) spiking_fused(
    const float* __restrict__ h0, const float* __restrict__ c0,
    const float* __restrict__ Whh, float* __restrict__ y,
    const float* __restrict__ x, const float* __restrict__ Wih,
    const float* __restrict__ bih, const float* __restrict__ bhh,
    int P, int S0)
{
    const int cta = blockIdx.x;
    const int tid = threadIdx.x;
    const unsigned nall = (unsigned)(NCTA2 + P);

    // ---- launch-start resets (CTA 0; ordered by init barrier) ----
    if (cta == 0) {
        if (tid < 8)  g_c1[tid] = 0u;
        if (tid == 8) g_c2 = 0u;
        if (tid == 9) g_gen2 = 0u;
        if (tid >= 16 && tid < 16 + MAXROWS) g_row_done[tid - 16] = 0u;
    }

    // =================== PRODUCER ROLE ===================
    if (cta >= NCTA2) {
        grid_barrier_atomic(nall);
        const int pid  = cta - NCTA2;
        const int rows = (T_STEPS - S0) / 2;      // tile-rows (2 steps each)
        float* As = sm;
        float* Bs = sm + 2 * BK * 132;
        for (int t = 0; t < rows * 32; t++) {
            if (t % P != pid) continue;
            const int r  = t >> 5;
            const int ct = t & 31;
            gemm_tile_body_512(x, Wih, bih, bhh,
                               S0 * BATCH + r * BM, ct * BN, As, Bs);
            __syncthreads();
            __threadfence();
            if (tid == 0) atomicAdd(&g_row_done[r], 1u);
            __syncthreads();
        }
        return;
    }

    // =================== RECURRENT ROLE ===================
    float* w_sm = sm;                       // w_sm[k*33 + col]
    float* hs   = sm + SM_W;                // hs[buf][warp][k_local][4]
    float* spk  = sm + SM_W + 2 * SM_HS;    // spk[b*33 + col]

    const int u0   = cta * UPC;
    const int col  = tid & 31;     // gate = col/8, u_local = col%8
    const int wrp  = tid >> 5;     // warp 0..15: batch rows 4w..4w+4
    const int lane = tid & 31;
    const int ub   = tid & 7;
    const int bb   = tid >> 3;     // 0..63: one (b,u) pair per thread

    // ---- load W_hh slice into persistent smem (one time) ----
    {
        const int wc  = tid & 31;                         // col 0..31
        const int sub = tid >> 5;                         // 0..15
        const int wrow = (wc >> 3) * HID + u0 + (wc & 7);
        const float* wp = Whh + (size_t)wrow * HID;
        for (int k0 = sub * 4; k0 < HID; k0 += 64) {
            float4 v = *(const float4*)&wp[k0];
            w_sm[(k0 + 0) * 33 + wc] = v.x;
            w_sm[(k0 + 1) * 33 + wc] = v.y;
            w_sm[(k0 + 2) * 33 + wc] = v.z;
            w_sm[(k0 + 3) * 33 + wc] = v.w;
        }
    }

    float c_r = c0[(size_t)bb * HID + u0 + ub];
    __stcg(&g_h[0][u0 + ub][bb], h0[(size_t)bb * HID + u0 + ub]);
    grid_barrier_atomic(nall);   // h[0] + resets visible; w_sm ready

    const int kl0 = lane * 4;    // per-warp staging: lane stages 4 k_locals

    for (int s = 0; s < T_STEPS; s++) {
        // gate on producer output for late steps (normally pre-satisfied)
        if (s >= S0) {
            if (tid == 0) {
                unsigned v;
                const unsigned* f = &g_row_done[(s - S0) >> 1];
                do {
                    asm volatile("ld.global.cg.u32 %0, [%1];" : "=r"(v) : "l"(f));
                    if (v < 32u) __nanosleep(128);
                } while (v < 32u);
            }
            __syncthreads();
        }

        const float* __restrict__ hprev = &g_h[s & 1][0][0];

        float xgv[4];
        {
            size_t base = (size_t)s * BATCH * G4 + (size_t)((col >> 3) * HID + u0 + (col & 7));
#pragma unroll
            for (int r = 0; r < 4; r++)
                xgv[r] = __ldcg(&g_xg[base + (size_t)(wrp * 4 + r) * G4]);
        }

        float acc[4];
#pragma unroll
        for (int r = 0; r < 4; r++) acc[r] = 0.0f;

        // prefetch chunk 0 (warp-private slice h[k][4w..4w+4))
        {
            const float* src = hprev + (size_t)kl0 * BATCH + wrp * 4;
            float* dst = hs + wrp * (KC * 4) + kl0 * 4;
#pragma unroll
            for (int j = 0; j < 4; j++)
                cp_async_cg16(dst + j * 4, src + j * BATCH);
            cp_async_commit();
        }

        for (int ic = 0; ic < HID / KC; ic++) {
            if (ic + 1 < HID / KC) {
                const float* src = hprev + (size_t)((ic + 1) * KC + kl0) * BATCH + wrp * 4;
                float* dst = hs + ((ic + 1) & 1) * SM_HS + wrp * (KC * 4) + kl0 * 4;
#pragma unroll
                for (int j = 0; j < 4; j++)
                    cp_async_cg16(dst + j * 4, src + j * BATCH);
                cp_async_commit();
                cp_async_wait<1>();
            } else {
                cp_async_wait<0>();
            }
            __syncwarp();

            const float* wk = w_sm + (ic * KC) * 33 + col;
            const float* hb = hs + (ic & 1) * SM_HS + wrp * (KC * 4);
#pragma unroll 8
            for (int k = 0; k < KC; k++) {
                float w = wk[k * 33];
                float4 p = *(const float4*)&hb[k * 4];   // broadcast
                acc[0] = __fmaf_rn(p.x, w, acc[0]);
                acc[1] = __fmaf_rn(p.y, w, acc[1]);
                acc[2] = __fmaf_rn(p.z, w, acc[2]);
                acc[3] = __fmaf_rn(p.w, w, acc[3]);
            }
            __syncwarp();
        }

        // z = xg + hg; spike
#pragma unroll
        for (int r = 0; r < 4; r++) {
            float z = __fadd_rn(xgv[r], acc[r]);
            spk[(wrp * 4 + r) * 33 + col] = (z >= 0.0f) ? 1.0f : 0.0f;
        }
        __syncthreads();

        // gate update: c' = f*c + i*g ; h' = o*c'  (exact 0/1-integer math)
        {
            float* hnext = &g_h[(s + 1) & 1][0][0];

            float i1 = spk[bb * 33 + ub],      f1 = spk[bb * 33 + 8 + ub];
            float g1 = spk[bb * 33 + 16 + ub], o1 = spk[bb * 33 + 24 + ub];
            c_r = __fadd_rn(__fmul_rn(f1, c_r), __fmul_rn(i1, g1));
            float hv = __fmul_rn(o1, c_r);
            y[((size_t)s * BATCH + bb) * HID + u0 + ub] = hv;
            __stcg(&hnext[(size_t)(u0 + ub) * BATCH + bb], hv);
        }

        step_barrier(cta, s);
    }
}

// ---------------- launch ----------------------------------------------------
extern "C" void kernel_launch(void* const* d_in, const int* in_sizes, int n_in,
                              void* d_out, int out_size) {
    const float* x   = (const float*)d_in[0];   // [T,B,I]
    const float* h0  = (const float*)d_in[1];   // [B,H]
    const float* c0  = (const float*)d_in[2];   // [B,H]
    const float* Wih = (const float*)d_in[3];   // [4H,I]
    const float* bih = (const float*)d_in[4];   // [4H]
    const float* Whh = (const float*)d_in[5];   // [4H,H]
    const float* bhh = (const float*)d_in[6];   // [4H]
    float* y = (float*)d_out;                   // [T,B,H]

    int sms = 0;
    cudaDeviceGetAttribute(&sms, cudaDevAttrMultiProcessorCount, 0);
    int P = sms - NCTA2;
    if (P > 20) P = 20;
    int PS = (P >= 16) ? 48 : (P >= 8 ? 16 : 0);
    if (PS == 0) P = 0;
    const int S0 = T_STEPS - PS;

    cudaFuncSetAttribute(spiking_fused,
                         cudaFuncAttributeMaxDynamicSharedMemorySize, SMEM_BYTES);

    gemm_xproj<<<dim3(G4 / BN, S0 / 2), 256>>>(x, Wih, bih, bhh);
    spiking_fused<<<NCTA2 + P, NT, SMEM_BYTES>>>(h0, c0, Whh, y,
                                                 x, Wih, bih, bhh, P, S0);
}

// round 16
// speedup vs baseline: 1.0383x; 1.0383x over previous
#include <cuda_runtime.h>
#include <cstdint>

#define T_STEPS 256
#define BATCH   64
#define INDIM   1024
#define HID     1024
#define G4      4096
#define NCTA2   128   // recurrent CTAs (all co-resident)
#define UPC     8     // hidden units per recurrent CTA
#define KC      128   // k-chunk for h staging
#define MAXROWS 24    // max producer tile-rows (PS=48 -> 24 rows)
#define WPITCH  1028  // w_sm pitch in floats (257 x 16B -> conflict-free)

// ---------------- scratch (static device globals; no allocs allowed) --------
__device__ float    g_xg[(size_t)T_STEPS * BATCH * G4];  // 256 MiB input projection
__device__ float    g_h[2][HID][BATCH];                  // TRANSPOSED [k][b], double buffered
__device__ unsigned g_bar_cnt;
__device__ unsigned g_bar_gen;
__device__ unsigned g_c1[8];            // two-level step barrier: group counters
__device__ unsigned g_c2;               // root counter
__device__ unsigned g_gen2;             // generation (== completed steps)
__device__ unsigned g_row_done[MAXROWS];// producer tile-row completion counters

// ---------------- init barrier (self-resetting, proven; used once) ----------
__device__ __forceinline__ void grid_barrier_atomic(unsigned nctas) {
    __syncthreads();
    __threadfence();
    if (threadIdx.x == 0) {
        unsigned gen = *(volatile unsigned*)&g_bar_gen;
        unsigned t = atomicAdd(&g_bar_cnt, 1u);
        if (t == nctas - 1u) {
            *(volatile unsigned*)&g_bar_cnt = 0u;
            __threadfence();
            atomicAdd(&g_bar_gen, 1u);
        } else {
            while (*(volatile unsigned*)&g_bar_gen == gen) { __nanosleep(64); }
        }
        __threadfence();
    }
    __syncthreads();
}

// ---------------- two-level per-step barrier (128 recurrent CTAs) -----------
__device__ __forceinline__ void step_barrier(int cta, int s) {
    __syncthreads();
    __threadfence();
    if (threadIdx.x == 0) {
        unsigned t = atomicAdd(&g_c1[cta >> 4], 1u);
        if (t == 16u * (unsigned)(s + 1) - 1u) {          // last of group
            unsigned t2 = atomicAdd(&g_c2, 1u);
            if (t2 == 8u * (unsigned)(s + 1) - 1u)        // last group
                atomicAdd(&g_gen2, 1u);
        }
        unsigned v;
        do {
            asm volatile("ld.global.cg.u32 %0, [%1];" : "=r"(v) : "l"(&g_gen2));
            if (v < (unsigned)(s + 1)) __nanosleep(32);
        } while (v < (unsigned)(s + 1));
    }
    __threadfence();
    __syncthreads();
}

// ---------------- cp.async helpers ------------------------------------------
__device__ __forceinline__ void cp_async_cg16(void* dst_smem, const void* src) {
    unsigned d = (unsigned)__cvta_generic_to_shared(dst_smem);
    asm volatile("cp.async.cg.shared.global [%0], [%1], 16;\n" :: "r"(d), "l"(src));
}
__device__ __forceinline__ void cp_async_commit() {
    asm volatile("cp.async.commit_group;\n");
}
template <int N>
__device__ __forceinline__ void cp_async_wait() {
    asm volatile("cp.async.wait_group %0;\n" :: "n"(N));
}

// ---------------- GEMM tile body (EXACT ORDER CONTRACT) ---------------------
// Per output element: single fp32 accumulator, sequential fused-FMA over
// k = 0..1023 ascending, then +b_ih, then +b_hh. Scalar FFMA only.
// Single __syncthreads per BK-iter (double buffering makes the 2nd redundant).
#define BM 128
#define BN 128
#define BK 16

__device__ __forceinline__ void gemm_tile_body(
    const float* __restrict__ x, const float* __restrict__ Wih,
    const float* __restrict__ bih, const float* __restrict__ bhh,
    int m0, int n0, float* As, float* Bs, bool cg_store)
{
    const int tid = threadIdx.x;
    const int tm  = tid >> 4;       // 0..15
    const int tn  = tid & 15;       // 0..15
    const int lk  = tid & 15;       // k lane (0..15)
    const int lr  = tid >> 4;       // row lane (0..15)

    float acc[8][8];
#pragma unroll
    for (int i = 0; i < 8; i++)
#pragma unroll
        for (int j = 0; j < 8; j++) acc[i][j] = 0.0f;

    float ra[8], rb[8];
#pragma unroll
    for (int p = 0; p < 8; p++) {
        ra[p] = x  [(size_t)(m0 + lr + p * 16) * INDIM + lk];
        rb[p] = Wih[(size_t)(n0 + lr + p * 16) * INDIM + lk];
    }

    for (int it = 0; it < INDIM / BK; it++) {
        const int buf = it & 1;
        float* Ab = As + (buf * BK) * 132;
        float* Bb = Bs + (buf * BK) * 132;
#pragma unroll
        for (int p = 0; p < 8; p++) {
            Ab[lk * 132 + lr + p * 16] = ra[p];
            Bb[lk * 132 + lr + p * 16] = rb[p];
        }
        __syncthreads();

        if (it + 1 < INDIM / BK) {
            const int k0 = (it + 1) * BK;
#pragma unroll
            for (int p = 0; p < 8; p++) {
                ra[p] = x  [(size_t)(m0 + lr + p * 16) * INDIM + k0 + lk];
                rb[p] = Wih[(size_t)(n0 + lr + p * 16) * INDIM + k0 + lk];
            }
        }

#pragma unroll
        for (int k = 0; k < BK; k++) {
            float4 a0 = *(const float4*)&Ab[k * 132 + tm * 8];
            float4 a1 = *(const float4*)&Ab[k * 132 + tm * 8 + 4];
            float4 b0 = *(const float4*)&Bb[k * 132 + tn * 8];
            float4 b1 = *(const float4*)&Bb[k * 132 + tn * 8 + 4];
            float av[8] = {a0.x, a0.y, a0.z, a0.w, a1.x, a1.y, a1.z, a1.w};
            float bv[8] = {b0.x, b0.y, b0.z, b0.w, b1.x, b1.y, b1.z, b1.w};
#pragma unroll
            for (int i = 0; i < 8; i++)
#pragma unroll
                for (int j = 0; j < 8; j++)
                    acc[i][j] = __fmaf_rn(av[i], bv[j], acc[i][j]);
        }
        // no trailing sync: next iter stages the OTHER buffer; the WAR on this
        // buffer is separated by the next iteration's post-staging sync.
    }

    float bi[8], bh[8];
#pragma unroll
    for (int j = 0; j < 8; j++) {
        int n = n0 + tn * 8 + j;
        bi[j] = bih[n];
        bh[j] = bhh[n];
    }
#pragma unroll
    for (int i = 0; i < 8; i++) {
        float v[8];
#pragma unroll
        for (int j = 0; j < 8; j++)
            v[j] = __fadd_rn(__fadd_rn(acc[i][j], bi[j]), bh[j]);
        size_t row = (size_t)(m0 + tm * 8 + i) * G4 + (n0 + tn * 8);
        float4 v0 = make_float4(v[0], v[1], v[2], v[3]);
        float4 v1 = make_float4(v[4], v[5], v[6], v[7]);
        if (cg_store) {
            __stcg((float4*)&g_xg[row],     v0);
            __stcg((float4*)&g_xg[row + 4], v1);
        } else {
            *(float4*)&g_xg[row]     = v0;
            *(float4*)&g_xg[row + 4] = v1;
        }
    }
}

// ---------------- Phase 1 standalone: steps [0, S0) -------------------------
__global__ void __launch_bounds__(256, 2) gemm_xproj(
    const float* __restrict__ x, const float* __restrict__ Wih,
    const float* __restrict__ bih, const float* __restrict__ bhh)
{
    __shared__ float As[2 * BK * 132];
    __shared__ float Bs[2 * BK * 132];
    gemm_tile_body(x, Wih, bih, bhh,
                   blockIdx.y * BM, blockIdx.x * BN, As, Bs, false);
}

// ---------------- Fused persistent kernel (256 threads) ---------------------
// CTAs [0,128): recurrence. CTAs [128,128+P): producers for steps [S0,256).
// w_sm is K-CONTIGUOUS per column (pitch 1028 floats): one LDS.128 fetches w
// for 4 k's, cutting k-loop LDS issues 12 -> 9 per warp per 4 k's.
#define SM_W    (32 * WPITCH)         // 32896 floats
#define SM_HS   (KC * BATCH)          // 8192 floats per buffer
#define SM_SPK  (BATCH * 33)
#define SMEM_BYTES ((SM_W + 2 * SM_HS + SM_SPK) * 4)   // 205568 B

extern __shared__ float sm[];

__global__ void __launch_bounds__(256, 1) spiking_fused(
    const float* __restrict__ h0, const float* __restrict__ c0,
    const float* __restrict__ Whh, float* __restrict__ y,
    const float* __restrict__ x, const float* __restrict__ Wih,
    const float* __restrict__ bih, const float* __restrict__ bhh,
    int P, int S0)
{
    const int cta = blockIdx.x;
    const int tid = threadIdx.x;
    const unsigned nall = (unsigned)(NCTA2 + P);

    // ---- launch-start resets (CTA 0; ordered by init barrier) ----
    if (cta == 0) {
        if (tid < 8)  g_c1[tid] = 0u;
        if (tid == 8) g_c2 = 0u;
        if (tid == 9) g_gen2 = 0u;
        if (tid >= 16 && tid < 16 + MAXROWS) g_row_done[tid - 16] = 0u;
    }

    // =================== PRODUCER ROLE ===================
    if (cta >= NCTA2) {
        grid_barrier_atomic(nall);
        const int pid  = cta - NCTA2;
        const int rows = (T_STEPS - S0) / 2;      // tile-rows (2 steps each)
        float* As = sm;
        float* Bs = sm + 2 * BK * 132;
        for (int t = 0; t < rows * 32; t++) {
            if (t % P != pid) continue;
            const int r  = t >> 5;
            const int ct = t & 31;
            gemm_tile_body(x, Wih, bih, bhh,
                           S0 * BATCH + r * BM, ct * BN, As, Bs, true);
            __syncthreads();
            __threadfence();
            if (tid == 0) atomicAdd(&g_row_done[r], 1u);
            __syncthreads();
        }
        return;
    }

    // =================== RECURRENT ROLE ===================
    float* w_sm = sm;                       // w_sm[col * WPITCH + k]
    float* hs   = sm + SM_W;                // hs[buf][warp][k_local][8]
    float* spk  = sm + SM_W + 2 * SM_HS;    // spk[b*33 + col]

    const int u0   = cta * UPC;
    const int col  = tid & 31;     // gate = col/8, u_local = col%8
    const int wrp  = tid >> 5;     // warp id == bgrp
    const int lane = tid & 31;
    const int ub   = tid & 7;
    const int bb   = tid >> 3;     // 0..31

    // ---- load W_hh slice into persistent smem, K-CONTIGUOUS (one time) ----
    {
        const int wc  = tid >> 3;                         // col 0..31
        const int sub = tid & 7;
        const int wrow = (wc >> 3) * HID + u0 + (wc & 7);
        const float* wp = Whh + (size_t)wrow * HID;
        for (int k0 = sub * 4; k0 < HID; k0 += 32) {
            float4 v = *(const float4*)&wp[k0];
            *(float4*)&w_sm[(size_t)wc * WPITCH + k0] = v;  // 16B-aligned
        }
    }

    float c_a = c0[(size_t)bb * HID + u0 + ub];
    float c_b = c0[(size_t)(bb + 32) * HID + u0 + ub];
    __stcg(&g_h[0][u0 + ub][bb],      h0[(size_t)bb * HID + u0 + ub]);
    __stcg(&g_h[0][u0 + ub][bb + 32], h0[(size_t)(bb + 32) * HID + u0 + ub]);
    grid_barrier_atomic(nall);   // h[0] + resets visible; w_sm ready

    const int kl0 = lane * 4;    // per-warp staging: lane stages 4 k_locals

    for (int s = 0; s < T_STEPS; s++) {
        // gate on producer output for late steps (normally pre-satisfied)
        if (s >= S0) {
            if (tid == 0) {
                unsigned v;
                const unsigned* f = &g_row_done[(s - S0) >> 1];
                do {
                    asm volatile("ld.global.cg.u32 %0, [%1];" : "=r"(v) : "l"(f));
                    if (v < 32u) __nanosleep(128);
                } while (v < 32u);
            }
            __syncthreads();
        }

        const float* __restrict__ hprev = &g_h[s & 1][0][0];

        float xgv[8];
        {
            size_t base = (size_t)s * BATCH * G4 + (size_t)((col >> 3) * HID + u0 + (col & 7));
#pragma unroll
            for (int r = 0; r < 8; r++)
                xgv[r] = __ldcg(&g_xg[base + (size_t)(wrp * 8 + r) * G4]);
        }

        float acc[8];
#pragma unroll
        for (int r = 0; r < 8; r++) acc[r] = 0.0f;

        // prefetch chunk 0 (warp-private slice h[k][8w..8w+8))
        {
            const float* src = hprev + (size_t)kl0 * BATCH + wrp * 8;
            float* dst = hs + wrp * (KC * 8) + kl0 * 8;
#pragma unroll
            for (int j = 0; j < 4; j++) {
                cp_async_cg16(dst + j * 8,     src + j * BATCH);
                cp_async_cg16(dst + j * 8 + 4, src + j * BATCH + 4);
            }
            cp_async_commit();
        }

        for (int ic = 0; ic < HID / KC; ic++) {
            if (ic + 1 < HID / KC) {
                const float* src = hprev + (size_t)((ic + 1) * KC + kl0) * BATCH + wrp * 8;
                float* dst = hs + ((ic + 1) & 1) * SM_HS + wrp * (KC * 8) + kl0 * 8;
#pragma unroll
                for (int j = 0; j < 4; j++) {
                    cp_async_cg16(dst + j * 8,     src + j * BATCH);
                    cp_async_cg16(dst + j * 8 + 4, src + j * BATCH + 4);
                }
                cp_async_commit();
                cp_async_wait<1>();
            } else {
                cp_async_wait<0>();
            }
            __syncwarp();

            const float* wk = w_sm + (size_t)col * WPITCH + ic * KC;
            const float* hb = hs + (ic & 1) * SM_HS + wrp * (KC * 8);
#pragma unroll 2
            for (int k4 = 0; k4 < KC; k4 += 4) {
                float4 wv = *(const float4*)&wk[k4];   // w for 4 k's, 1 LDS.128
                float4 p, q;

                p = *(const float4*)&hb[(k4 + 0) * 8];
                q = *(const float4*)&hb[(k4 + 0) * 8 + 4];
                acc[0] = __fmaf_rn(p.x, wv.x, acc[0]);
                acc[1] = __fmaf_rn(p.y, wv.x, acc[1]);
                acc[2] = __fmaf_rn(p.z, wv.x, acc[2]);
                acc[3] = __fmaf_rn(p.w, wv.x, acc[3]);
                acc[4] = __fmaf_rn(q.x, wv.x, acc[4]);
                acc[5] = __fmaf_rn(q.y, wv.x, acc[5]);
                acc[6] = __fmaf_rn(q.z, wv.x, acc[6]);
                acc[7] = __fmaf_rn(q.w, wv.x, acc[7]);

                p = *(const float4*)&hb[(k4 + 1) * 8];
                q = *(const float4*)&hb[(k4 + 1) * 8 + 4];
                acc[0] = __fmaf_rn(p.x, wv.y, acc[0]);
                acc[1] = __fmaf_rn(p.y, wv.y, acc[1]);
                acc[2] = __fmaf_rn(p.z, wv.y, acc[2]);
                acc[3] = __fmaf_rn(p.w, wv.y, acc[3]);
                acc[4] = __fmaf_rn(q.x, wv.y, acc[4]);
                acc[5] = __fmaf_rn(q.y, wv.y, acc[5]);
                acc[6] = __fmaf_rn(q.z, wv.y, acc[6]);
                acc[7] = __fmaf_rn(q.w, wv.y, acc[7]);

                p = *(const float4*)&hb[(k4 + 2) * 8];
                q = *(const float4*)&hb[(k4 + 2) * 8 + 4];
                acc[0] = __fmaf_rn(p.x, wv.z, acc[0]);
                acc[1] = __fmaf_rn(p.y, wv.z, acc[1]);
                acc[2] = __fmaf_rn(p.z, wv.z, acc[2]);
                acc[3] = __fmaf_rn(p.w, wv.z, acc[3]);
                acc[4] = __fmaf_rn(q.x, wv.z, acc[4]);
                acc[5] = __fmaf_rn(q.y, wv.z, acc[5]);
                acc[6] = __fmaf_rn(q.z, wv.z, acc[6]);
                acc[7] = __fmaf_rn(q.w, wv.z, acc[7]);

                p = *(const float4*)&hb[(k4 + 3) * 8];
                q = *(const float4*)&hb[(k4 + 3) * 8 + 4];
                acc[0] = __fmaf_rn(p.x, wv.w, acc[0]);
                acc[1] = __fmaf_rn(p.y, wv.w, acc[1]);
                acc[2] = __fmaf_rn(p.z, wv.w, acc[2]);
                acc[3] = __fmaf_rn(p.w, wv.w, acc[3]);
                acc[4] = __fmaf_rn(q.x, wv.w, acc[4]);
                acc[5] = __fmaf_rn(q.y, wv.w, acc[5]);
                acc[6] = __fmaf_rn(q.z, wv.w, acc[6]);
                acc[7] = __fmaf_rn(q.w, wv.w, acc[7]);
            }
            __syncwarp();
        }

        // z = xg + hg; spike
#pragma unroll
        for (int r = 0; r < 8; r++) {
            float z = __fadd_rn(xgv[r], acc[r]);
            spk[(wrp * 8 + r) * 33 + col] = (z >= 0.0f) ? 1.0f : 0.0f;
        }
        __syncthreads();

        // gate update: c' = f*c + i*g ; h' = o*c'  (exact 0/1-integer math)
        {
            float* hnext = &g_h[(s + 1) & 1][0][0];

            float i1 = spk[bb * 33 + ub],      f1 = spk[bb * 33 + 8 + ub];
            float g1 = spk[bb * 33 + 16 + ub], o1 = spk[bb * 33 + 24 + ub];
            c_a = __fadd_rn(__fmul_rn(f1, c_a), __fmul_rn(i1, g1));
            float ha = __fmul_rn(o1, c_a);
            y[((size_t)s * BATCH + bb) * HID + u0 + ub] = ha;
            __stcg(&hnext[(size_t)(u0 + ub) * BATCH + bb], ha);

            float i2 = spk[(bb + 32) * 33 + ub],      f2 = spk[(bb + 32) * 33 + 8 + ub];
            float g2 = spk[(bb + 32) * 33 + 16 + ub], o2 = spk[(bb + 32) * 33 + 24 + ub];
            c_b = __fadd_rn(__fmul_rn(f2, c_b), __fmul_rn(i2, g2));
            float hb2 = __fmul_rn(o2, c_b);
            y[((size_t)s * BATCH + bb + 32) * HID + u0 + ub] = hb2;
            __stcg(&hnext[(size_t)(u0 + ub) * BATCH + bb + 32], hb2);
        }

        step_barrier(cta, s);
    }
}

// ---------------- launch ----------------------------------------------------
extern "C" void kernel_launch(void* const* d_in, const int* in_sizes, int n_in,
                              void* d_out, int out_size) {
    const float* x   = (const float*)d_in[0];   // [T,B,I]
    const float* h0  = (const float*)d_in[1];   // [B,H]
    const float* c0  = (const float*)d_in[2];   // [B,H]
    const float* Wih = (const float*)d_in[3];   // [4H,I]
    const float* bih = (const float*)d_in[4];   // [4H]
    const float* Whh = (const float*)d_in[5];   // [4H,H]
    const float* bhh = (const float*)d_in[6];   // [4H]
    float* y = (float*)d_out;                   // [T,B,H]

    int sms = 0;
    cudaDeviceGetAttribute(&sms, cudaDevAttrMultiProcessorCount, 0);
    int P = sms - NCTA2;
    if (P > 20) P = 20;
    int PS = (P >= 16) ? 48 : (P >= 8 ? 16 : 0);
    if (PS == 0) P = 0;
    const int S0 = T_STEPS - PS;

    cudaFuncSetAttribute(spiking_fused,
                         cudaFuncAttributeMaxDynamicSharedMemorySize, SMEM_BYTES);

    gemm_xproj<<<dim3(G4 / BN, S0 / 2), 256>>>(x, Wih, bih, bhh);
    spiking_fused<<<NCTA2 + P, 256, SMEM_BYTES>>>(h0, c0, Whh, y,
                                                  x, Wih, bih, bhh, P, S0);
}